// round 5
// baseline (speedup 1.0000x reference)
#include <cuda_runtime.h>

// Problem constants
#define B_  16
#define D_  256
#define T_  2048
#define N_  (B_ * T_)   // 32768 rows
#define K_  8192

// Output layout in d_out (flat float32): [quantized 8388608][loss 1][idx 32768]
#define Q_ELEMS   (B_ * D_ * T_)
#define LOSS_OFF  Q_ELEMS
#define IDX_OFF   (Q_ELEMS + 1)

// Device scratch (no allocations allowed)
__device__ float g_enorm[K_];
__device__ float g_znorm[N_];
__device__ int   g_idx[N_];
__device__ float g_partial[N_ / 128];

typedef unsigned long long u64;

// Packed f32x2 FMA: two independent fma.rn lanes (bit-exact per lane).
__device__ __forceinline__ u64 fma2(u64 a, u64 b, u64 c) {
    u64 d;
    asm("fma.rn.f32x2 %0, %1, %2, %3;" : "=l"(d) : "l"(a), "l"(b), "l"(c));
    return d;
}
__device__ __forceinline__ u64 pack2(float x, float y) {
    u64 d;
    asm("mov.b64 %0, {%1, %2};" : "=l"(d) : "f"(x), "f"(y));
    return d;
}
__device__ __forceinline__ void unpack2(u64 v, float& lo, float& hi) {
    asm("mov.b64 {%0, %1}, %2;" : "=f"(lo), "=f"(hi) : "l"(v));
}

// ---------------------------------------------------------------------------
// Kernel 1a: e_norm[k] = sum_d emb[k,d]^2.  Order irrelevant for matching
// (perturbation ~1e-13 vs ulp(256)=3e-5 bucket grid) -> fast warp reduce.
// ---------------------------------------------------------------------------
__global__ void enorm_kernel(const float* __restrict__ emb) {
    int gw   = (blockIdx.x * blockDim.x + threadIdx.x) >> 5;
    int lane = threadIdx.x & 31;
    if (gw >= K_) return;
    const float4* row = reinterpret_cast<const float4*>(emb + (size_t)gw * D_);
    float s = 0.f;
    #pragma unroll
    for (int i = 0; i < 2; i++) {
        float4 v = row[lane + 32 * i];
        s += v.x * v.x + v.y * v.y + v.z * v.z + v.w * v.w;
    }
    #pragma unroll
    for (int o = 16; o > 0; o >>= 1) s += __shfl_xor_sync(0xffffffffu, s, o);
    if (lane == 0) g_enorm[gw] = s;
}

// ---------------------------------------------------------------------------
// Kernel 1b: z_norm[n] = sum_d z[b,d,t]^2, SEQUENTIAL over d with separately
// rounded squares (matches XLA square + single-accumulator reduce).
// ---------------------------------------------------------------------------
__global__ __launch_bounds__(256)
void znorm_kernel(const float* __restrict__ z) {
    int n = blockIdx.x * 256 + threadIdx.x;
    int b = n / T_;
    int t = n % T_;
    const float* base = z + (size_t)b * D_ * T_ + t;
    float s = 0.f;
    #pragma unroll 8
    for (int d = 0; d < D_; d++) {
        float v = base[(size_t)d * T_];
        s = __fadd_rn(s, __fmul_rn(v, v));   // no FMA: square rounded first
    }
    g_znorm[n] = s;
}

// ---------------------------------------------------------------------------
// Kernel 2: fused distance-GEMM + argmin with packed f32x2 FMA.
// dist[m][k] = fl( fl(znorm[m] + enorm[k]) - fl(2 * dot) ); dot is a
// sequential ascending-d fp32 FMA chain per output (each f32x2 lane is an
// independent chain -> bit-identical to the scalar version).
// ---------------------------------------------------------------------------
#define BM 128
#define BN 128
#define BK 16
#define TM 8
#define TN 8

__global__ __launch_bounds__(256, 2)
void vq_argmin_kernel(const float* __restrict__ z,
                      const float* __restrict__ emb,
                      float* __restrict__ d_out) {
    __shared__ float As[BK][BM];       // As[d][m] = zf[m][d]
    __shared__ float Bs[BK][BN];       // Bs[d][k]
    __shared__ float En[BN];
    __shared__ float Zn[BM];
    __shared__ float rmin[BM];
    __shared__ int   ridx[BM];

    const int n0 = blockIdx.x * BM;
    const int b  = n0 / T_;
    const int t0 = n0 % T_;
    const float* zb = z + (size_t)b * D_ * T_ + t0;   // zb[d * T_ + m]

    const int tid = threadIdx.x;
    const int tx  = tid & 15;          // code-tile column group
    const int ty  = tid >> 4;          // row group

    if (tid < BM) {
        rmin[tid] = 3.4e38f;
        ridx[tid] = 0;
        Zn[tid]   = g_znorm[n0 + tid];
    }

    // Load-index precompute
    const int a_dd = tid >> 4;         // 0..15 (d row of As)
    const int a_mq = (tid & 15) * 4;   // float4 offset in m
    const int b_kk = tid >> 1;         // 0..127 (code row)
    const int b_dq = (tid & 1) * 8;    // d offset 0 or 8

    for (int kt = 0; kt < K_; kt += BN) {
        __syncthreads();                       // prev epilogue done reading En
        if (tid < BN) En[tid] = g_enorm[kt + tid];

        u64 acc[TM][TN / 2];                   // pairs (j, j+1) per lane
        #pragma unroll
        for (int i = 0; i < TM; i++)
            #pragma unroll
            for (int jp = 0; jp < TN / 2; jp++) acc[i][jp] = 0ull;

        for (int d0 = 0; d0 < D_; d0 += BK) {
            __syncthreads();                   // prev compute done reading As/Bs
            // --- load z tile: 16 threads per d-row, 2 float4 each ---
            const float* zrow = zb + (size_t)(d0 + a_dd) * T_;
            *(float4*)&As[a_dd][a_mq]      = *(const float4*)&zrow[a_mq];
            *(float4*)&As[a_dd][64 + a_mq] = *(const float4*)&zrow[64 + a_mq];
            // --- load emb tile transposed: 1 code row per 2 threads ---
            const float* erow = emb + (size_t)(kt + b_kk) * D_ + d0 + b_dq;
            float4 v0 = *(const float4*)&erow[0];
            float4 v1 = *(const float4*)&erow[4];
            Bs[b_dq + 0][b_kk] = v0.x; Bs[b_dq + 1][b_kk] = v0.y;
            Bs[b_dq + 2][b_kk] = v0.z; Bs[b_dq + 3][b_kk] = v0.w;
            Bs[b_dq + 4][b_kk] = v1.x; Bs[b_dq + 5][b_kk] = v1.y;
            Bs[b_dq + 6][b_kk] = v1.z; Bs[b_dq + 7][b_kk] = v1.w;
            __syncthreads();
            // --- compute: strictly ascending d, one FMA chain per output ---
            #pragma unroll
            for (int d = 0; d < BK; d++) {
                float a[TM];
                *(float4*)&a[0] = *(const float4*)&As[d][ty * TM];
                *(float4*)&a[4] = *(const float4*)&As[d][ty * TM + 4];
                u64 b2[TN / 2];
                const u64* bp = reinterpret_cast<const u64*>(&Bs[d][tx * TN]);
                #pragma unroll
                for (int jp = 0; jp < TN / 2; jp++) b2[jp] = bp[jp];
                #pragma unroll
                for (int i = 0; i < TM; i++) {
                    u64 da = pack2(a[i], a[i]);
                    #pragma unroll
                    for (int jp = 0; jp < TN / 2; jp++)
                        acc[i][jp] = fma2(da, b2[jp], acc[i][jp]);
                }
            }
        }

        // --- epilogue: replicate reference rounding, per-row argmin ---
        #pragma unroll
        for (int i = 0; i < TM; i++) {
            const float zn = Zn[ty * TM + i];
            float bv = 3.4e38f;
            int   bj = 0;
            #pragma unroll
            for (int jp = 0; jp < TN / 2; jp++) {
                float alo, ahi;
                unpack2(acc[i][jp], alo, ahi);
                float vlo = __fsub_rn(__fadd_rn(zn, En[tx * TN + 2 * jp]),
                                      __fmul_rn(2.f, alo));
                float vhi = __fsub_rn(__fadd_rn(zn, En[tx * TN + 2 * jp + 1]),
                                      __fmul_rn(2.f, ahi));
                if (vlo < bv) { bv = vlo; bj = 2 * jp; }      // strict <: lowest j wins
                if (vhi < bv) { bv = vhi; bj = 2 * jp + 1; }
            }
            int bk = kt + tx * TN + bj;
            // reduce across the 16 tx lanes (same 16-lane half of the warp)
            #pragma unroll
            for (int o = 1; o < 16; o <<= 1) {
                float ov = __shfl_xor_sync(0xffffffffu, bv, o);
                int   ok = __shfl_xor_sync(0xffffffffu, bk, o);
                if (ov < bv || (ov == bv && ok < bk)) { bv = ov; bk = ok; }
            }
            if (tx == 0) {
                int m = ty * TM + i;
                if (bv < rmin[m]) { rmin[m] = bv; ridx[m] = bk; }  // earlier tile wins ties
            }
        }
    }

    __syncthreads();
    if (tid < BM) {
        int n = n0 + tid;
        g_idx[n] = ridx[tid];
        d_out[IDX_OFF + n] = (float)ridx[tid];
    }
}

// ---------------------------------------------------------------------------
// Kernel 3: straight-through output + per-block loss partial.
// out = fl(z + fl(q - z))  (must replicate the ST estimator's rounding).
// ---------------------------------------------------------------------------
__global__ __launch_bounds__(256)
void gather_kernel(const float* __restrict__ z,
                   const float* __restrict__ emb,
                   float* __restrict__ d_out) {
    __shared__ int   sidx[128];
    __shared__ float red[256];
    const int n0 = blockIdx.x * 128;
    const int b  = n0 / T_;
    const int t0 = n0 % T_;
    const int tid = threadIdx.x;

    if (tid < 128) sidx[tid] = g_idx[n0 + tid];
    __syncthreads();

    float local = 0.f;
    for (int e = tid; e < 128 * D_; e += 256) {
        int m = e & 127;
        int d = e >> 7;
        float q = emb[(size_t)sidx[m] * D_ + d];        // L2-resident gather
        size_t off = (size_t)b * D_ * T_ + (size_t)d * T_ + t0 + m;
        float zv = z[off];
        float df = __fsub_rn(q, zv);                    // fl(q - z)
        d_out[off] = __fadd_rn(zv, df);                 // fl(z + fl(q - z))
        local = __fmaf_rn(df, df, local);
    }
    red[tid] = local;
    __syncthreads();
    #pragma unroll
    for (int s = 128; s > 0; s >>= 1) {
        if (tid < s) red[tid] += red[tid + s];
        __syncthreads();
    }
    if (tid == 0) g_partial[blockIdx.x] = red[0];
}

// ---------------------------------------------------------------------------
// Kernel 4: loss = 1.25 * mean((q - z)^2)   (deterministic tree reduce)
// ---------------------------------------------------------------------------
__global__ void loss_kernel(float* __restrict__ d_out) {
    __shared__ float red[256];
    int tid = threadIdx.x;
    red[tid] = g_partial[tid];    // exactly 256 partials
    __syncthreads();
    #pragma unroll
    for (int s = 128; s > 0; s >>= 1) {
        if (tid < s) red[tid] += red[tid + s];
        __syncthreads();
    }
    if (tid == 0)
        d_out[LOSS_OFF] = 1.25f * red[0] / (float)((size_t)N_ * D_);
}

// ---------------------------------------------------------------------------
extern "C" void kernel_launch(void* const* d_in, const int* in_sizes, int n_in,
                              void* d_out, int out_size) {
    const float* z   = (const float*)d_in[0];
    const float* emb = (const float*)d_in[1];
    float* out = (float*)d_out;
    (void)in_sizes; (void)n_in; (void)out_size;

    enorm_kernel<<<K_ * 32 / 256, 256>>>(emb);
    znorm_kernel<<<N_ / 256, 256>>>(z);
    vq_argmin_kernel<<<N_ / BM, 256>>>(z, emb, out);
    gather_kernel<<<N_ / 128, 256>>>(z, emb, out);
    loss_kernel<<<1, 256>>>(out);
}